// round 15
// baseline (speedup 1.0000x reference)
#include <cuda_runtime.h>
#include <cstdint>

#define BB 4
#define SS 8192
#define HH 16
#define DD 64
#define WW 128
#define CC 64

constexpr int NT = 256;

// bf16 tiles [128 rows][64 cols], row stride 72 halves (144B -> ldmatrix conflict-free)
constexpr int TILE_B = 128 * 144;         // 18432 bytes per (hi or lo) tile
constexpr int OFF_QH = 0;
constexpr int OFF_QL = OFF_QH + TILE_B;
constexpr int OFF_KH = OFF_QL + TILE_B;   // lo always at +TILE_B from hi
constexpr int OFF_KL = OFF_KH + TILE_B;
constexpr int OFF_VH = OFF_KL + TILE_B;
constexpr int OFF_VL = OFF_VH + TILE_B;
constexpr int SMEM_BYTES = OFF_VL + TILE_B;   // 110592 -> 2 CTAs/SM

// fp32 staging tile for the coalesced out store: 128 x 72 floats in the (dead) V region
constexpr int OFF_STG = OFF_VH;
constexpr int STG_STRIDE = 72;

__device__ __forceinline__ uint32_t smem_u32(const void* p) {
    uint32_t a;
    asm("{ .reg .u64 t; cvta.to.shared.u64 t, %1; cvt.u32.u64 %0, t; }" : "=r"(a) : "l"(p));
    return a;
}
__device__ __forceinline__ uint32_t cvt_bf16x2(float up, float lo) {   // {hi16=up, lo16=lo}
    uint32_t r;
    asm("cvt.rn.bf16x2.f32 %0, %1, %2;" : "=r"(r) : "f"(up), "f"(lo));
    return r;
}
__device__ __forceinline__ void ldm4(uint32_t r[4], uint32_t a) {
    asm volatile("ldmatrix.sync.aligned.m8n8.x4.shared.b16 {%0,%1,%2,%3}, [%4];"
                 : "=r"(r[0]), "=r"(r[1]), "=r"(r[2]), "=r"(r[3]) : "r"(a));
}
__device__ __forceinline__ void ldm4t(uint32_t r[4], uint32_t a) {
    asm volatile("ldmatrix.sync.aligned.m8n8.x4.trans.shared.b16 {%0,%1,%2,%3}, [%4];"
                 : "=r"(r[0]), "=r"(r[1]), "=r"(r[2]), "=r"(r[3]) : "r"(a));
}
__device__ __forceinline__ void mma16816(float c[4], const uint32_t a[4],
                                         uint32_t b0, uint32_t b1) {
    asm volatile("mma.sync.aligned.m16n8k16.row.col.f32.bf16.bf16.f32 "
                 "{%0,%1,%2,%3}, {%4,%5,%6,%7}, {%8,%9}, {%0,%1,%2,%3};"
                 : "+f"(c[0]), "+f"(c[1]), "+f"(c[2]), "+f"(c[3])
                 : "r"(a[0]), "r"(a[1]), "r"(a[2]), "r"(a[3]), "r"(b0), "r"(b1));
}

// FMA-pipe exp (avoids MUFU bottleneck). |x| <= ~90 here; rel err ~3e-6.
__device__ __forceinline__ float fexp(float x) {
    float t = x * 1.4426950408889634f;
    float r = __fadd_rn(t, 12582912.0f);        // round-to-nearest-int trick
    float n = __fsub_rn(r, 12582912.0f);
    float f = __fsub_rn(t, n);
    float p = 1.3333558e-3f;
    p = fmaf(p, f, 9.6181291e-3f);
    p = fmaf(p, f, 5.5504109e-2f);
    p = fmaf(p, f, 2.4022651e-1f);
    p = fmaf(p, f, 6.9314718e-1f);
    p = fmaf(p, f, 1.0f);
    int e = (int)n;
    return __int_as_float(__float_as_int(p) + (e << 23));
}

// gmem fp32 [128 rows x 64] -> smem bf16 hi/lo tiles (lo at dstH + TILE_B)
__device__ __forceinline__ void load_split(char* smc, int dstH, const float* gbase, int tid) {
    #pragma unroll
    for (int it = 0; it < 8; ++it) {
        int idx = tid + it * 256;
        int r = idx >> 4, d0 = (idx & 15) << 2;
        float4 t = *(const float4*)(gbase + (size_t)r * 1024 + d0);
        uint32_t h0 = cvt_bf16x2(t.y, t.x);
        uint32_t h1 = cvt_bf16x2(t.w, t.z);
        float f0 = __uint_as_float(h0 << 16);
        float f1 = __uint_as_float(h0 & 0xffff0000u);
        float f2 = __uint_as_float(h1 << 16);
        float f3 = __uint_as_float(h1 & 0xffff0000u);
        uint32_t l0 = cvt_bf16x2(t.y - f1, t.x - f0);
        uint32_t l1 = cvt_bf16x2(t.w - f3, t.z - f2);
        int off = r * 144 + d0 * 2;
        *(uint2*)(smc + dstH + off) = make_uint2(h0, h1);
        *(uint2*)(smc + dstH + TILE_B + off) = make_uint2(l0, l1);
    }
}

// S tile [16 rows x 64 cols]: 3-product bf16 split QK. qBase/kBase2 are lane-adjusted.
__device__ __forceinline__ void qk_tile(float pc[8][4], uint32_t qBase, uint32_t kBase2) {
    #pragma unroll
    for (int ks = 0; ks < 4; ++ks) {
        uint32_t qh[4], ql[4];
        ldm4(qh, qBase + ks * 32);
        ldm4(ql, qBase + TILE_B + ks * 32);
        #pragma unroll
        for (int np = 0; np < 4; ++np) {
            uint32_t kh[4], kl[4];
            uint32_t ka = kBase2 + np * (16 * 144) + ks * 32;
            ldm4(kh, ka);
            ldm4(kl, ka + TILE_B);
            mma16816(pc[2*np],   qh, kh[0], kh[1]);
            mma16816(pc[2*np],   qh, kl[0], kl[1]);
            mma16816(pc[2*np],   ql, kh[0], kh[1]);
            mma16816(pc[2*np+1], qh, kh[2], kh[3]);
            mma16816(pc[2*np+1], qh, kl[2], kl[3]);
            mma16816(pc[2*np+1], ql, kh[2], kh[3]);
        }
    }
}

// pass-2 variant: Q fragments pre-hoisted in registers
__device__ __forceinline__ void qk_hoisted(float pc[8][4],
        const uint32_t qfh[4][4], const uint32_t qfl[4][4], uint32_t kBase2) {
    #pragma unroll
    for (int ks = 0; ks < 4; ++ks) {
        #pragma unroll
        for (int np = 0; np < 4; ++np) {
            uint32_t kh[4], kl[4];
            uint32_t ka = kBase2 + np * (16 * 144) + ks * 32;
            ldm4(kh, ka);
            ldm4(kl, ka + TILE_B);
            mma16816(pc[2*np],   qfh[ks], kh[0], kh[1]);
            mma16816(pc[2*np],   qfh[ks], kl[0], kl[1]);
            mma16816(pc[2*np],   qfl[ks], kh[0], kh[1]);
            mma16816(pc[2*np+1], qfh[ks], kh[2], kh[3]);
            mma16816(pc[2*np+1], qfh[ks], kl[2], kl[3]);
            mma16816(pc[2*np+1], qfl[ks], kh[2], kh[3]);
        }
    }
}

// O += P(unnormalized exp, in C-frag regs) @ V, 3-product split; P->A frag in registers
__device__ __forceinline__ void pv_tile(float o[8][4], const float pc[8][4], uint32_t vBase2) {
    #pragma unroll
    for (int kt = 0; kt < 4; ++kt) {
        uint32_t ahi[4], alo[4];
        #pragma unroll
        for (int hf = 0; hf < 2; ++hf) {
            const float* s = pc[2 * kt + hf];
            uint32_t hA = cvt_bf16x2(s[1], s[0]);
            uint32_t hB = cvt_bf16x2(s[3], s[2]);
            float l0 = s[0] - __uint_as_float(hA << 16);
            float l1 = s[1] - __uint_as_float(hA & 0xffff0000u);
            float l2 = s[2] - __uint_as_float(hB << 16);
            float l3 = s[3] - __uint_as_float(hB & 0xffff0000u);
            ahi[2*hf+0] = hA;                 ahi[2*hf+1] = hB;
            alo[2*hf+0] = cvt_bf16x2(l1, l0); alo[2*hf+1] = cvt_bf16x2(l3, l2);
        }
        #pragma unroll
        for (int dp = 0; dp < 4; ++dp) {
            uint32_t vh[4], vl[4];
            uint32_t va = vBase2 + kt * (16 * 144) + dp * 32;
            ldm4t(vh, va);
            ldm4t(vl, va + TILE_B);
            mma16816(o[2*dp],   ahi, vh[0], vh[1]);
            mma16816(o[2*dp],   ahi, vl[0], vl[1]);
            mma16816(o[2*dp],   alo, vh[0], vh[1]);
            mma16816(o[2*dp+1], ahi, vh[2], vh[3]);
            mma16816(o[2*dp+1], ahi, vl[2], vl[3]);
            mma16816(o[2*dp+1], alo, vh[2], vh[3]);
        }
    }
}

__global__ void __launch_bounds__(NT, 2)
swa_mma(const float* __restrict__ q, const float* __restrict__ k,
        const float* __restrict__ v, float* __restrict__ out,
        float* __restrict__ attn)
{
    extern __shared__ char smc[];
    const uint32_t sb = smem_u32(smc);
    const int tid = threadIdx.x;
    const int w = tid >> 5, ln = tid & 31;
    const int c = blockIdx.x, h = blockIdx.y, b = blockIdx.z;
    const int s0 = c * WW;
    const int rw = w * 16;                      // warp's first query row

    // lane-dependent ldmatrix base offsets
    const uint32_t qBase = sb + OFF_QH + (rw + (ln & 15)) * 144 + ((ln >> 4) & 1) * 16;
    const uint32_t kLane = (ln & 7) * 144 + ((ln >> 4) & 1) * (8 * 144) + ((ln >> 3) & 1) * 16;
    const uint32_t vLane = (ln & 7) * 144 + ((ln >> 3) & 1) * (8 * 144) + ((ln >> 4) & 1) * 16;

    // load Q (hi/lo) once
    load_split(smc, OFF_QH, q + ((size_t)(b * SS + s0) * HH + h) * DD, tid);
    __syncthreads();

    float o[8][4];
    #pragma unroll
    for (int i = 0; i < 8; ++i)
        #pragma unroll
        for (int j = 0; j < 4; ++j) o[i][j] = 0.f;
    float s0sum = 0.f, s1sum = 0.f;
    int ninv = 0;

    const int r0g = rw + (ln >> 2);             // thread's first owned row (second is +8)

    // -------- pass 1: QK -> exp -> rowsums + unnormalized PV --------
    for (int e = 0; e < 3; ++e) {
        const int ce = c + e - 1;
        if ((unsigned)ce >= (unsigned)CC) { ++ninv; continue; }
        __syncthreads();   // prior K/V reads complete before overwrite
        load_split(smc, OFF_KH, k + ((size_t)(b * SS + ce * WW) * HH + h) * DD, tid);
        load_split(smc, OFF_VH, v + ((size_t)(b * SS + ce * WW) * HH + h) * DD, tid);
        __syncthreads();
        for (int h2 = 0; h2 < 2; ++h2) {
            float pc[8][4];
            #pragma unroll
            for (int i = 0; i < 8; ++i)
                #pragma unroll
                for (int j = 0; j < 4; ++j) pc[i][j] = 0.f;
            qk_tile(pc, qBase, sb + OFF_KH + kLane + h2 * (64 * 144));
            #pragma unroll
            for (int p = 0; p < 8; ++p) {
                pc[p][0] = fexp(pc[p][0]); pc[p][1] = fexp(pc[p][1]);
                pc[p][2] = fexp(pc[p][2]); pc[p][3] = fexp(pc[p][3]);
                s0sum += pc[p][0] + pc[p][1];
                s1sum += pc[p][2] + pc[p][3];
            }
            pv_tile(o, pc, sb + OFF_VH + vLane + h2 * (64 * 144));
        }
    }
    // row sums: reduce across the 4 lanes sharing a row
    s0sum += __shfl_xor_sync(0xffffffffu, s0sum, 1);
    s0sum += __shfl_xor_sync(0xffffffffu, s0sum, 2);
    s1sum += __shfl_xor_sync(0xffffffffu, s1sum, 1);
    s1sum += __shfl_xor_sync(0xffffffffu, s1sum, 2);
    s0sum += 128.0f * ninv;          // padded chunks contribute exp(0)=1 per column
    s1sum += 128.0f * ninv;
    const float inv0 = 1.0f / s0sum;
    const float inv1 = 1.0f / s1sum;

    // valid neighbor-chunk list for pass 2
    int ve[3], nv = 0;
    #pragma unroll
    for (int e = 0; e < 3; ++e) {
        const int ce = c + e - 1;
        if ((unsigned)ce < (unsigned)CC) ve[nv++] = e;
    }

    float* stg = (float*)(smc + OFF_STG);       // [128][STG_STRIDE] fp32 (V region, now dead)

    // -------- O store: fragments -> stage -> coalesced 256B rows --------
    __syncthreads();                            // all pass-1 smem reads done (V area free)
    #pragma unroll
    for (int dt = 0; dt < 8; ++dt) {
        int col = dt * 8 + 2 * (ln & 3);
        *(float2*)&stg[r0g * STG_STRIDE + col] =
            make_float2(o[dt][0] * inv0, o[dt][1] * inv0);
        *(float2*)&stg[(r0g + 8) * STG_STRIDE + col] =
            make_float2(o[dt][2] * inv1, o[dt][3] * inv1);
    }
    __syncthreads();
    {
        // cooperative out store (reads VH-region stage) + FIRST pass-2 K load (KH region)
        const int rr = tid >> 4, cc4 = (tid & 15) << 2;   // 16 threads/row, float4 each
        float* obase = out + ((size_t)(b * SS + s0) * HH + h) * DD;
        #pragma unroll
        for (int it = 0; it < 8; ++it) {
            int row = rr + it * 16;
            float4 vv = *(float4*)&stg[row * STG_STRIDE + cc4];
            *(float4*)(obase + (size_t)row * (HH * DD) + cc4) = vv;
        }
        load_split(smc, OFF_KH, k + ((size_t)(b * SS + (c + ve[0] - 1) * WW) * HH + h) * DD, tid);
    }

    // hoist Q fragments for all of pass 2 (o regs are dead -> budget free)
    uint32_t qfh[4][4], qfl[4][4];
    #pragma unroll
    for (int ks = 0; ks < 4; ++ks) {
        ldm4(qfh[ks], qBase + ks * 32);
        ldm4(qfl[ks], qBase + TILE_B + ks * 32);
    }

    float* attnbase = attn + ((size_t)(b * SS + s0) * HH + h) * 384;
    float* arow0 = attnbase + (size_t)r0g * (HH * 384) + 2 * (ln & 3);
    float* arow1 = arow0 + (size_t)8 * (HH * 384);

    // boundary chunks: probs are exactly inv (exp(0)/sum); write straight from registers
    if (nv < 3) {
        const int e = (c == 0) ? 0 : 2;
        float* g0 = attnbase + (size_t)r0g * (HH * 384) + e * 128;
        float* g1 = g0 + (size_t)8 * (HH * 384);
        const float4 f0 = make_float4(inv0, inv0, inv0, inv0);
        const float4 f1 = make_float4(inv1, inv1, inv1, inv1);
        #pragma unroll
        for (int j = 0; j < 8; ++j) {
            int cc4 = (4 * j + (ln & 3)) << 2;   // 4 lanes -> 64B contiguous
            *(float4*)(g0 + cc4) = f0;
            *(float4*)(g1 + cc4) = f1;
        }
    }

    __syncthreads();    // first K ready (KH); VH free for prefetch

    // -------- pass 2: double-buffered K (KH <-> VH), Q frags hoisted --------
    for (int i = 0; i < nv; ++i) {
        if (i + 1 < nv) {
            // prefetch next chunk into the other buffer; overlaps current compute
            const int nb = (i & 1) ? OFF_KH : OFF_VH;
            load_split(smc, nb, k + ((size_t)(b * SS + (c + ve[i + 1] - 1) * WW) * HH + h) * DD, tid);
        }
        const int cb = (i & 1) ? OFF_VH : OFF_KH;
        const int e = ve[i];
        #pragma unroll
        for (int h2 = 0; h2 < 2; ++h2) {
            float pc[8][4];
            #pragma unroll
            for (int ii = 0; ii < 8; ++ii)
                #pragma unroll
                for (int j = 0; j < 4; ++j) pc[ii][j] = 0.f;
            qk_hoisted(pc, qfh, qfl, sb + cb + kLane + h2 * (64 * 144));
            #pragma unroll
            for (int p = 0; p < 8; ++p) {
                int col = e * 128 + h2 * 64 + p * 8;
                *(float2*)(arow0 + col) =
                    make_float2(fexp(pc[p][0]) * inv0, fexp(pc[p][1]) * inv0);
                *(float2*)(arow1 + col) =
                    make_float2(fexp(pc[p][2]) * inv1, fexp(pc[p][3]) * inv1);
            }
        }
        __syncthreads();   // next buffer fully written + current buffer fully read
    }
}

extern "C" void kernel_launch(void* const* d_in, const int* in_sizes, int n_in,
                              void* d_out, int out_size) {
    const float* q = (const float*)d_in[0];
    const float* k = (const float*)d_in[1];
    const float* v = (const float*)d_in[2];
    float* out  = (float*)d_out;
    float* attn = out + (size_t)BB * SS * HH * DD;   // tuple order: (out, attn)

    cudaFuncSetAttribute(swa_mma, cudaFuncAttributeMaxDynamicSharedMemorySize, SMEM_BYTES);
    dim3 grid(CC, HH, BB);
    swa_mma<<<grid, NT, SMEM_BYTES>>>(q, k, v, out, attn);
}

// round 16
// speedup vs baseline: 1.6325x; 1.6325x over previous
#include <cuda_runtime.h>
#include <cstdint>

#define BB 4
#define SS 8192
#define HH 16
#define DD 64
#define WW 128
#define CC 64

constexpr int NT = 256;

// bf16 tiles [128 rows][64 cols], row stride 72 halves (144B -> ldmatrix conflict-free)
constexpr int TILE_B = 128 * 144;         // 18432 bytes per (hi or lo) tile
constexpr int OFF_QH = 0;
constexpr int OFF_QL = OFF_QH + TILE_B;
constexpr int OFF_KH = OFF_QL + TILE_B;   // lo always at +TILE_B from hi
constexpr int OFF_KL = OFF_KH + TILE_B;
constexpr int OFF_VH = OFF_KL + TILE_B;
constexpr int OFF_VL = OFF_VH + TILE_B;
constexpr int SMEM_BYTES = OFF_VL + TILE_B;   // 110592 -> 2 CTAs/SM

__device__ __forceinline__ uint32_t smem_u32(const void* p) {
    uint32_t a;
    asm("{ .reg .u64 t; cvta.to.shared.u64 t, %1; cvt.u32.u64 %0, t; }" : "=r"(a) : "l"(p));
    return a;
}
__device__ __forceinline__ uint32_t cvt_bf16x2(float up, float lo) {   // {hi16=up, lo16=lo}
    uint32_t r;
    asm("cvt.rn.bf16x2.f32 %0, %1, %2;" : "=r"(r) : "f"(up), "f"(lo));
    return r;
}
__device__ __forceinline__ void ldm4(uint32_t r[4], uint32_t a) {
    asm volatile("ldmatrix.sync.aligned.m8n8.x4.shared.b16 {%0,%1,%2,%3}, [%4];"
                 : "=r"(r[0]), "=r"(r[1]), "=r"(r[2]), "=r"(r[3]) : "r"(a));
}
__device__ __forceinline__ void ldm4t(uint32_t r[4], uint32_t a) {
    asm volatile("ldmatrix.sync.aligned.m8n8.x4.trans.shared.b16 {%0,%1,%2,%3}, [%4];"
                 : "=r"(r[0]), "=r"(r[1]), "=r"(r[2]), "=r"(r[3]) : "r"(a));
}
__device__ __forceinline__ void mma16816(float c[4], const uint32_t a[4],
                                         uint32_t b0, uint32_t b1) {
    asm volatile("mma.sync.aligned.m16n8k16.row.col.f32.bf16.bf16.f32 "
                 "{%0,%1,%2,%3}, {%4,%5,%6,%7}, {%8,%9}, {%0,%1,%2,%3};"
                 : "+f"(c[0]), "+f"(c[1]), "+f"(c[2]), "+f"(c[3])
                 : "r"(a[0]), "r"(a[1]), "r"(a[2]), "r"(a[3]), "r"(b0), "r"(b1));
}

// FMA-pipe exp (avoids MUFU bottleneck). |x| <= ~90 here; rel err ~3e-6.
__device__ __forceinline__ float fexp(float x) {
    float t = x * 1.4426950408889634f;
    float r = __fadd_rn(t, 12582912.0f);        // round-to-nearest-int trick
    float n = __fsub_rn(r, 12582912.0f);
    float f = __fsub_rn(t, n);
    float p = 1.3333558e-3f;
    p = fmaf(p, f, 9.6181291e-3f);
    p = fmaf(p, f, 5.5504109e-2f);
    p = fmaf(p, f, 2.4022651e-1f);
    p = fmaf(p, f, 6.9314718e-1f);
    p = fmaf(p, f, 1.0f);
    int e = (int)n;
    return __int_as_float(__float_as_int(p) + (e << 23));
}

__device__ __forceinline__ void split_store(char* smc, int dstH, int off, float4 t) {
    uint32_t h0 = cvt_bf16x2(t.y, t.x);
    uint32_t h1 = cvt_bf16x2(t.w, t.z);
    float f0 = __uint_as_float(h0 << 16);
    float f1 = __uint_as_float(h0 & 0xffff0000u);
    float f2 = __uint_as_float(h1 << 16);
    float f3 = __uint_as_float(h1 & 0xffff0000u);
    uint32_t l0 = cvt_bf16x2(t.y - f1, t.x - f0);
    uint32_t l1 = cvt_bf16x2(t.w - f3, t.z - f2);
    *(uint2*)(smc + dstH + off) = make_uint2(h0, h1);
    *(uint2*)(smc + dstH + TILE_B + off) = make_uint2(l0, l1);
}

// gmem fp32 [128 rows x 64] -> smem bf16 hi/lo tiles (lo at dstH + TILE_B)
__device__ __forceinline__ void load_split(char* smc, int dstH, const float* gbase, int tid) {
    #pragma unroll
    for (int it = 0; it < 8; ++it) {
        int idx = tid + it * 256;
        int r = idx >> 4, d0 = (idx & 15) << 2;
        float4 t = *(const float4*)(gbase + (size_t)r * 1024 + d0);
        split_store(smc, dstH, r * 144 + d0 * 2, t);
    }
}

// fused K+V load: interleaved LDGs double the in-flight memory parallelism
__device__ __forceinline__ void load_split_kv(char* smc, const float* kbase,
                                              const float* vbase, int tid) {
    #pragma unroll
    for (int it = 0; it < 4; ++it) {
        int idxA = tid + (2 * it) * 256;
        int idxB = tid + (2 * it + 1) * 256;
        int rA = idxA >> 4, dA = (idxA & 15) << 2;
        int rB = idxB >> 4, dB = (idxB & 15) << 2;
        float4 tkA = *(const float4*)(kbase + (size_t)rA * 1024 + dA);
        float4 tvA = *(const float4*)(vbase + (size_t)rA * 1024 + dA);
        float4 tkB = *(const float4*)(kbase + (size_t)rB * 1024 + dB);
        float4 tvB = *(const float4*)(vbase + (size_t)rB * 1024 + dB);
        split_store(smc, OFF_KH, rA * 144 + dA * 2, tkA);
        split_store(smc, OFF_VH, rA * 144 + dA * 2, tvA);
        split_store(smc, OFF_KH, rB * 144 + dB * 2, tkB);
        split_store(smc, OFF_VH, rB * 144 + dB * 2, tvB);
    }
}

// S tile [16 rows x 64 cols]: 3-product bf16 split QK, accumulator-interleaved issue.
// Per-accumulator order stays hh -> hl -> lh (bitwise-identical results).
__device__ __forceinline__ void qk_tile(float pc[8][4], uint32_t qBase, uint32_t kBase2) {
    #pragma unroll
    for (int ks = 0; ks < 4; ++ks) {
        uint32_t qh[4], ql[4];
        ldm4(qh, qBase + ks * 32);
        ldm4(ql, qBase + TILE_B + ks * 32);
        #pragma unroll
        for (int np = 0; np < 4; ++np) {
            uint32_t kh[4], kl[4];
            uint32_t ka = kBase2 + np * (16 * 144) + ks * 32;
            ldm4(kh, ka);
            ldm4(kl, ka + TILE_B);
            mma16816(pc[2*np],   qh, kh[0], kh[1]);
            mma16816(pc[2*np+1], qh, kh[2], kh[3]);
            mma16816(pc[2*np],   qh, kl[0], kl[1]);
            mma16816(pc[2*np+1], qh, kl[2], kl[3]);
            mma16816(pc[2*np],   ql, kh[0], kh[1]);
            mma16816(pc[2*np+1], ql, kh[2], kh[3]);
        }
    }
}

// O += P(unnormalized exp, in C-frag regs) @ V, 3-product split; P->A frag in registers
__device__ __forceinline__ void pv_tile(float o[8][4], const float pc[8][4], uint32_t vBase2) {
    #pragma unroll
    for (int kt = 0; kt < 4; ++kt) {
        uint32_t ahi[4], alo[4];
        #pragma unroll
        for (int hf = 0; hf < 2; ++hf) {
            const float* s = pc[2 * kt + hf];
            uint32_t hA = cvt_bf16x2(s[1], s[0]);
            uint32_t hB = cvt_bf16x2(s[3], s[2]);
            float l0 = s[0] - __uint_as_float(hA << 16);
            float l1 = s[1] - __uint_as_float(hA & 0xffff0000u);
            float l2 = s[2] - __uint_as_float(hB << 16);
            float l3 = s[3] - __uint_as_float(hB & 0xffff0000u);
            ahi[2*hf+0] = hA;                 ahi[2*hf+1] = hB;
            alo[2*hf+0] = cvt_bf16x2(l1, l0); alo[2*hf+1] = cvt_bf16x2(l3, l2);
        }
        #pragma unroll
        for (int dp = 0; dp < 4; ++dp) {
            uint32_t vh[4], vl[4];
            uint32_t va = vBase2 + kt * (16 * 144) + dp * 32;
            ldm4t(vh, va);
            ldm4t(vl, va + TILE_B);
            mma16816(o[2*dp],   ahi, vh[0], vh[1]);
            mma16816(o[2*dp+1], ahi, vh[2], vh[3]);
            mma16816(o[2*dp],   ahi, vl[0], vl[1]);
            mma16816(o[2*dp+1], ahi, vl[2], vl[3]);
            mma16816(o[2*dp],   alo, vh[0], vh[1]);
            mma16816(o[2*dp+1], alo, vh[2], vh[3]);
        }
    }
}

__global__ void __launch_bounds__(NT, 2)
swa_mma(const float* __restrict__ q, const float* __restrict__ k,
        const float* __restrict__ v, float* __restrict__ out,
        float* __restrict__ attn)
{
    extern __shared__ char smc[];
    const uint32_t sb = smem_u32(smc);
    const int tid = threadIdx.x;
    const int w = tid >> 5, ln = tid & 31;
    const int c = blockIdx.x, h = blockIdx.y, b = blockIdx.z;
    const int s0 = c * WW;
    const int rw = w * 16;                      // warp's first query row

    // lane-dependent ldmatrix base offsets
    const uint32_t qBase = sb + OFF_QH + (rw + (ln & 15)) * 144 + ((ln >> 4) & 1) * 16;
    const uint32_t kLane = (ln & 7) * 144 + ((ln >> 4) & 1) * (8 * 144) + ((ln >> 3) & 1) * 16;
    const uint32_t vLane = (ln & 7) * 144 + ((ln >> 3) & 1) * (8 * 144) + ((ln >> 4) & 1) * 16;

    // load Q (hi/lo) once
    load_split(smc, OFF_QH, q + ((size_t)(b * SS + s0) * HH + h) * DD, tid);
    __syncthreads();

    float o[8][4];
    #pragma unroll
    for (int i = 0; i < 8; ++i)
        #pragma unroll
        for (int j = 0; j < 4; ++j) o[i][j] = 0.f;
    float s0sum = 0.f, s1sum = 0.f;
    int ninv = 0;

    const int r0g = rw + (ln >> 2);

    // -------- pass 1: QK -> exp -> rowsums + unnormalized PV --------
    for (int e = 0; e < 3; ++e) {
        const int ce = c + e - 1;
        if ((unsigned)ce >= (unsigned)CC) { ++ninv; continue; }
        __syncthreads();   // prior K/V reads complete before overwrite
        load_split_kv(smc, k + ((size_t)(b * SS + ce * WW) * HH + h) * DD,
                           v + ((size_t)(b * SS + ce * WW) * HH + h) * DD, tid);
        __syncthreads();
        for (int h2 = 0; h2 < 2; ++h2) {
            float pc[8][4];
            #pragma unroll
            for (int i = 0; i < 8; ++i)
                #pragma unroll
                for (int j = 0; j < 4; ++j) pc[i][j] = 0.f;
            qk_tile(pc, qBase, sb + OFF_KH + kLane + h2 * (64 * 144));
            #pragma unroll
            for (int p = 0; p < 8; ++p) {
                pc[p][0] = fexp(pc[p][0]); pc[p][1] = fexp(pc[p][1]);
                pc[p][2] = fexp(pc[p][2]); pc[p][3] = fexp(pc[p][3]);
                s0sum += pc[p][0] + pc[p][1];
                s1sum += pc[p][2] + pc[p][3];
            }
            pv_tile(o, pc, sb + OFF_VH + vLane + h2 * (64 * 144));
        }
    }
    // row sums: reduce across the 4 lanes sharing a row
    s0sum += __shfl_xor_sync(0xffffffffu, s0sum, 1);
    s0sum += __shfl_xor_sync(0xffffffffu, s0sum, 2);
    s1sum += __shfl_xor_sync(0xffffffffu, s1sum, 1);
    s1sum += __shfl_xor_sync(0xffffffffu, s1sum, 2);
    s0sum += 128.0f * ninv;          // padded chunks contribute exp(0)=1 per column
    s1sum += 128.0f * ninv;
    const float inv0 = 1.0f / s0sum;
    const float inv1 = 1.0f / s1sum;

    // -------- O = O_unnorm * inv, store --------
    {
        float* orow0 = out + ((size_t)(b * SS + s0 + r0g) * HH + h) * DD + 2 * (ln & 3);
        float* orow1 = orow0 + (size_t)8 * HH * DD;
        #pragma unroll
        for (int dt = 0; dt < 8; ++dt) {
            *(float2*)(orow0 + dt * 8) = make_float2(o[dt][0] * inv0, o[dt][1] * inv0);
            *(float2*)(orow1 + dt * 8) = make_float2(o[dt][2] * inv1, o[dt][3] * inv1);
        }
    }

    // -------- pass 2: recompute QK -> exp -> normalized attn --------
    float* arow0 = attn + ((size_t)(b * SS + s0 + r0g) * HH + h) * 384 + 2 * (ln & 3);
    float* arow1 = arow0 + (size_t)8 * HH * 384;
    for (int e = 0; e < 3; ++e) {
        const int ce = c + e - 1;
        if ((unsigned)ce < (unsigned)CC) {
            __syncthreads();
            load_split(smc, OFF_KH, k + ((size_t)(b * SS + ce * WW) * HH + h) * DD, tid);
            __syncthreads();
            for (int h2 = 0; h2 < 2; ++h2) {
                float pc[8][4];
                #pragma unroll
                for (int i = 0; i < 8; ++i)
                    #pragma unroll
                    for (int j = 0; j < 4; ++j) pc[i][j] = 0.f;
                qk_tile(pc, qBase, sb + OFF_KH + kLane + h2 * (64 * 144));
                #pragma unroll
                for (int p = 0; p < 8; ++p) {
                    int col = e * 128 + h2 * 64 + p * 8;
                    *(float2*)(arow0 + col) =
                        make_float2(fexp(pc[p][0]) * inv0, fexp(pc[p][1]) * inv0);
                    *(float2*)(arow1 + col) =
                        make_float2(fexp(pc[p][2]) * inv1, fexp(pc[p][3]) * inv1);
                }
            }
        } else {
            const float2 f0 = make_float2(inv0, inv0);
            const float2 f1 = make_float2(inv1, inv1);
            #pragma unroll
            for (int p8 = 0; p8 < 16; ++p8) {
                int col = e * 128 + p8 * 8;
                *(float2*)(arow0 + col) = f0;
                *(float2*)(arow1 + col) = f1;
            }
        }
    }
}

extern "C" void kernel_launch(void* const* d_in, const int* in_sizes, int n_in,
                              void* d_out, int out_size) {
    const float* q = (const float*)d_in[0];
    const float* k = (const float*)d_in[1];
    const float* v = (const float*)d_in[2];
    float* out  = (float*)d_out;
    float* attn = out + (size_t)BB * SS * HH * DD;   // tuple order: (out, attn)

    cudaFuncSetAttribute(swa_mma, cudaFuncAttributeMaxDynamicSharedMemorySize, SMEM_BYTES);
    dim3 grid(CC, HH, BB);
    swa_mma<<<grid, NT, SMEM_BYTES>>>(q, k, v, out, attn);
}